// round 1
// baseline (speedup 1.0000x reference)
#include <cuda_runtime.h>
#include <cstdint>

#define NB 2
#define SQ 2048
#define DM 1024
#define NH 16
#define DK 64

constexpr size_t QKV_ELEMS = (size_t)NB * NH * SQ * DK;   // 4,194,304
constexpr size_t CTX_ELEMS = (size_t)NB * SQ * DM;        // 4,194,304
constexpr size_t OUT_ELEMS = (size_t)NB * SQ * DM;        // 4,194,304
constexpr size_t ATTN_ELEMS = (size_t)NB * NH * SQ * SQ;  // 134,217,728

__device__ float g_q[QKV_ELEMS];
__device__ float g_k[QKV_ELEMS];
__device__ float g_v[QKV_ELEMS];
__device__ float g_ctx[CTX_ELEMS];

__device__ __forceinline__ uint32_t f2tf(float x) {
    uint32_t r;
    asm("cvt.rna.tf32.f32 %0, %1;" : "=r"(r) : "f"(x));
    return r;
}
__device__ __forceinline__ float f2tff(float x) { return __uint_as_float(f2tf(x)); }

__device__ __forceinline__ void mma8(float* c, const uint32_t* a, const uint32_t* b) {
    asm volatile(
        "mma.sync.aligned.m16n8k8.row.col.f32.tf32.tf32.f32 "
        "{%0,%1,%2,%3},{%4,%5,%6,%7},{%8,%9},{%0,%1,%2,%3};"
        : "+f"(c[0]), "+f"(c[1]), "+f"(c[2]), "+f"(c[3])
        : "r"(a[0]), "r"(a[1]), "r"(a[2]), "r"(a[3]), "r"(b[0]), "r"(b[1]));
}

// ============================================================================
// GEMM: C = A @ W^T + bias.  A [4096,1024] row-major, W [1024,1024] row-major.
// MODE 1: blockIdx.z selects (A,W,bias) among the three QKV projections; output
//         written head-split into g_q/g_k/g_v as [B,H,S,DK].
// MODE 0: A = g_ctx, output row-major [4096,1024] to outp.
// Block tile 128x128, BK=32, 256 threads (8 warps as 4m x 2n, warp tile 32x64).
// ============================================================================
template <int MODE>
__global__ __launch_bounds__(256) void gemm_kernel(
    const float* __restrict__ A0, const float* __restrict__ A1, const float* __restrict__ A2,
    const float* __restrict__ W0, const float* __restrict__ W1, const float* __restrict__ W2,
    const float* __restrict__ b0, const float* __restrict__ b1, const float* __restrict__ b2,
    float* __restrict__ outp)
{
    __shared__ float As[128][36];
    __shared__ float Ws[128][36];

    const int tid = threadIdx.x;
    const int warp = tid >> 5, lane = tid & 31;
    const int g = lane >> 2, tg = lane & 3;
    const int warp_m = warp & 3, warp_n = warp >> 2;
    const int z = (MODE == 1) ? blockIdx.z : 0;

    const float* Aptr;
    const float* Wm;
    const float* bias;
    if (MODE == 1) {
        Aptr = (z == 0) ? A0 : (z == 1) ? A1 : A2;
        Wm   = (z == 0) ? W0 : (z == 1) ? W1 : W2;
        bias = (z == 0) ? b0 : (z == 1) ? b1 : b2;
    } else {
        Aptr = g_ctx; Wm = W0; bias = b0;
    }

    const int rowA0 = blockIdx.y * 128;
    const int col0  = blockIdx.x * 128;

    float acc[2][8][4];
#pragma unroll
    for (int mt = 0; mt < 2; mt++)
#pragma unroll
        for (int nt = 0; nt < 8; nt++)
#pragma unroll
            for (int c = 0; c < 4; c++) acc[mt][nt][c] = 0.f;

    for (int k0 = 0; k0 < DM; k0 += 32) {
        __syncthreads();
#pragma unroll
        for (int i = 0; i < 4; i++) {
            int lin = tid + i * 256;
            int r = lin >> 3, c4 = lin & 7;
            float4 va = *(const float4*)(Aptr + (size_t)(rowA0 + r) * DM + k0 + c4 * 4);
            As[r][c4 * 4 + 0] = f2tff(va.x);
            As[r][c4 * 4 + 1] = f2tff(va.y);
            As[r][c4 * 4 + 2] = f2tff(va.z);
            As[r][c4 * 4 + 3] = f2tff(va.w);
            float4 vw = *(const float4*)(Wm + (size_t)(col0 + r) * DM + k0 + c4 * 4);
            Ws[r][c4 * 4 + 0] = f2tff(vw.x);
            Ws[r][c4 * 4 + 1] = f2tff(vw.y);
            Ws[r][c4 * 4 + 2] = f2tff(vw.z);
            Ws[r][c4 * 4 + 3] = f2tff(vw.w);
        }
        __syncthreads();
#pragma unroll
        for (int ks8 = 0; ks8 < 4; ks8++) {
            const int kk = ks8 * 8;
            uint32_t af[2][4];
#pragma unroll
            for (int mt = 0; mt < 2; mt++) {
                int r = warp_m * 32 + mt * 16 + g;
                af[mt][0] = __float_as_uint(As[r][kk + tg]);
                af[mt][1] = __float_as_uint(As[r + 8][kk + tg]);
                af[mt][2] = __float_as_uint(As[r][kk + tg + 4]);
                af[mt][3] = __float_as_uint(As[r + 8][kk + tg + 4]);
            }
#pragma unroll
            for (int nt = 0; nt < 8; nt++) {
                int n = warp_n * 64 + nt * 8 + g;
                uint32_t bf[2] = {__float_as_uint(Ws[n][kk + tg]),
                                  __float_as_uint(Ws[n][kk + tg + 4])};
#pragma unroll
                for (int mt = 0; mt < 2; mt++) mma8(acc[mt][nt], af[mt], bf);
            }
        }
    }

#pragma unroll
    for (int mt = 0; mt < 2; mt++) {
        int row = rowA0 + warp_m * 32 + mt * 16 + g;
#pragma unroll
        for (int nt = 0; nt < 8; nt++) {
            int col = col0 + warp_n * 64 + nt * 8 + tg * 2;
            float bv0 = bias[col], bv1 = bias[col + 1];
            float c0 = acc[mt][nt][0] + bv0, c1 = acc[mt][nt][1] + bv1;
            float c2 = acc[mt][nt][2] + bv0, c3 = acc[mt][nt][3] + bv1;
            if (MODE == 0) {
                *(float2*)(outp + (size_t)row * DM + col) = make_float2(c0, c1);
                *(float2*)(outp + (size_t)(row + 8) * DM + col) = make_float2(c2, c3);
            } else {
                float* dst = (z == 0) ? g_q : (z == 1) ? g_k : g_v;
                int b_ = row >> 11, s_ = row & 2047;
                int h_ = col >> 6, d_ = col & 63;
                size_t base = (((size_t)b_ * NH + h_) * SQ + s_) * DK + d_;
                *(float2*)(dst + base) = make_float2(c0, c1);
                *(float2*)(dst + base + 8 * DK) = make_float2(c2, c3);
            }
        }
    }
}

// ============================================================================
// Fused attention. One block = one (b,h) x 64-row q-tile. 128 threads (4 warps,
// 16 q-rows/warp). Two passes over K tiles of 128:
//   pass 1: exact online rowmax m and rowsum l.
//   pass 2: recompute S, write normalized attn to gmem, accumulate ctx = P @ V.
// Dynamic smem: qs 64x68 + ks 128x68 (K then reused for V) + ps 64x132 = 86016 B.
// ============================================================================
__global__ __launch_bounds__(128) void attn_kernel(float* __restrict__ attn_out)
{
    extern __shared__ float sm[];
    float(*qs)[68] = (float(*)[68])sm;
    float(*ks)[68] = (float(*)[68])(sm + 64 * 68);
    float(*ps)[132] = (float(*)[132])(sm + 64 * 68 + 128 * 68);

    const int tid = threadIdx.x;
    const int warp = tid >> 5, lane = tid & 31;
    const int g = lane >> 2, tg = lane & 3;
    const int qt = blockIdx.x, bh = blockIdx.y;
    const int wrow = warp * 16;

    const float* qb = g_q + ((size_t)bh * SQ + qt * 64) * DK;
    const float* kb = g_k + (size_t)bh * SQ * DK;
    const float* vb = g_v + (size_t)bh * SQ * DK;

    // load q tile (tf32-rounded)
#pragma unroll
    for (int i = 0; i < 8; i++) {
        int lin = tid + i * 128;
        int r = lin >> 4, c4 = lin & 15;
        float4 v = *(const float4*)(qb + (size_t)r * DK + c4 * 4);
        qs[r][c4 * 4 + 0] = f2tff(v.x);
        qs[r][c4 * 4 + 1] = f2tff(v.y);
        qs[r][c4 * 4 + 2] = f2tff(v.z);
        qs[r][c4 * 4 + 3] = f2tff(v.w);
    }
    __syncthreads();

    float sacc[16][4];
    float m0 = -1e30f, m1 = -1e30f, l0 = 0.f, l1 = 0.f;

    // ---------------- PASS 1: row max + row sum ----------------
    for (int kt = 0; kt < 16; kt++) {
#pragma unroll
        for (int i = 0; i < 16; i++) {
            int lin = tid + i * 128;
            int r = lin >> 4, c4 = lin & 15;
            float4 v = *(const float4*)(kb + ((size_t)kt * 128 + r) * DK + c4 * 4);
            ks[r][c4 * 4 + 0] = f2tff(v.x);
            ks[r][c4 * 4 + 1] = f2tff(v.y);
            ks[r][c4 * 4 + 2] = f2tff(v.z);
            ks[r][c4 * 4 + 3] = f2tff(v.w);
        }
        __syncthreads();

#pragma unroll
        for (int nt = 0; nt < 16; nt++)
#pragma unroll
            for (int c = 0; c < 4; c++) sacc[nt][c] = 0.f;
#pragma unroll
        for (int d8 = 0; d8 < 8; d8++) {
            const int c0 = d8 * 8;
            uint32_t a[4];
            a[0] = __float_as_uint(qs[wrow + g][c0 + tg]);
            a[1] = __float_as_uint(qs[wrow + 8 + g][c0 + tg]);
            a[2] = __float_as_uint(qs[wrow + g][c0 + tg + 4]);
            a[3] = __float_as_uint(qs[wrow + 8 + g][c0 + tg + 4]);
#pragma unroll
            for (int nt = 0; nt < 16; nt++) {
                uint32_t b[2] = {__float_as_uint(ks[nt * 8 + g][c0 + tg]),
                                 __float_as_uint(ks[nt * 8 + g][c0 + tg + 4])};
                mma8(sacc[nt], a, b);
            }
        }

        float tm0 = -1e30f, tm1 = -1e30f;
#pragma unroll
        for (int nt = 0; nt < 16; nt++) {
#pragma unroll
            for (int c = 0; c < 4; c++) sacc[nt][c] *= 0.125f;
            tm0 = fmaxf(tm0, fmaxf(sacc[nt][0], sacc[nt][1]));
            tm1 = fmaxf(tm1, fmaxf(sacc[nt][2], sacc[nt][3]));
        }
        tm0 = fmaxf(tm0, __shfl_xor_sync(0xffffffffu, tm0, 1));
        tm0 = fmaxf(tm0, __shfl_xor_sync(0xffffffffu, tm0, 2));
        tm1 = fmaxf(tm1, __shfl_xor_sync(0xffffffffu, tm1, 1));
        tm1 = fmaxf(tm1, __shfl_xor_sync(0xffffffffu, tm1, 2));

        float nm0 = fmaxf(m0, tm0), nm1 = fmaxf(m1, tm1);
        l0 *= __expf(m0 - nm0);
        l1 *= __expf(m1 - nm1);
        float s0 = 0.f, s1 = 0.f;
#pragma unroll
        for (int nt = 0; nt < 16; nt++) {
            s0 += __expf(sacc[nt][0] - nm0) + __expf(sacc[nt][1] - nm0);
            s1 += __expf(sacc[nt][2] - nm1) + __expf(sacc[nt][3] - nm1);
        }
        s0 += __shfl_xor_sync(0xffffffffu, s0, 1);
        s0 += __shfl_xor_sync(0xffffffffu, s0, 2);
        s1 += __shfl_xor_sync(0xffffffffu, s1, 1);
        s1 += __shfl_xor_sync(0xffffffffu, s1, 2);
        l0 += s0; l1 += s1; m0 = nm0; m1 = nm1;
        __syncthreads();
    }

    const float inv0 = 1.f / l0, inv1 = 1.f / l1;
    float ctx[8][4];
#pragma unroll
    for (int nt = 0; nt < 8; nt++)
#pragma unroll
        for (int c = 0; c < 4; c++) ctx[nt][c] = 0.f;

    // ---------------- PASS 2: write attn + accumulate ctx ----------------
    for (int kt = 0; kt < 16; kt++) {
#pragma unroll
        for (int i = 0; i < 16; i++) {
            int lin = tid + i * 128;
            int r = lin >> 4, c4 = lin & 15;
            float4 v = *(const float4*)(kb + ((size_t)kt * 128 + r) * DK + c4 * 4);
            ks[r][c4 * 4 + 0] = f2tff(v.x);
            ks[r][c4 * 4 + 1] = f2tff(v.y);
            ks[r][c4 * 4 + 2] = f2tff(v.z);
            ks[r][c4 * 4 + 3] = f2tff(v.w);
        }
        __syncthreads();

#pragma unroll
        for (int nt = 0; nt < 16; nt++)
#pragma unroll
            for (int c = 0; c < 4; c++) sacc[nt][c] = 0.f;
#pragma unroll
        for (int d8 = 0; d8 < 8; d8++) {
            const int c0 = d8 * 8;
            uint32_t a[4];
            a[0] = __float_as_uint(qs[wrow + g][c0 + tg]);
            a[1] = __float_as_uint(qs[wrow + 8 + g][c0 + tg]);
            a[2] = __float_as_uint(qs[wrow + g][c0 + tg + 4]);
            a[3] = __float_as_uint(qs[wrow + 8 + g][c0 + tg + 4]);
#pragma unroll
            for (int nt = 0; nt < 16; nt++) {
                uint32_t b[2] = {__float_as_uint(ks[nt * 8 + g][c0 + tg]),
                                 __float_as_uint(ks[nt * 8 + g][c0 + tg + 4])};
                mma8(sacc[nt], a, b);
            }
        }

        const size_t arow0 = ((size_t)bh * SQ + qt * 64 + wrow + g) * SQ + kt * 128;
        const size_t arow1 = arow0 + (size_t)8 * SQ;
#pragma unroll
        for (int nt = 0; nt < 16; nt++) {
            float p00 = __expf(sacc[nt][0] * 0.125f - m0) * inv0;
            float p01 = __expf(sacc[nt][1] * 0.125f - m0) * inv0;
            float p10 = __expf(sacc[nt][2] * 0.125f - m1) * inv1;
            float p11 = __expf(sacc[nt][3] * 0.125f - m1) * inv1;
            int cc = nt * 8 + tg * 2;
            *(float2*)(attn_out + arow0 + cc) = make_float2(p00, p01);
            *(float2*)(attn_out + arow1 + cc) = make_float2(p10, p11);
            *(float2*)(&ps[wrow + g][cc]) = make_float2(f2tff(p00), f2tff(p01));
            *(float2*)(&ps[wrow + 8 + g][cc]) = make_float2(f2tff(p10), f2tff(p11));
        }
        __syncthreads();  // all warps done reading K tile

        // load V tile into ks
#pragma unroll
        for (int i = 0; i < 16; i++) {
            int lin = tid + i * 128;
            int r = lin >> 4, c4 = lin & 15;
            float4 v = *(const float4*)(vb + ((size_t)kt * 128 + r) * DK + c4 * 4);
            ks[r][c4 * 4 + 0] = f2tff(v.x);
            ks[r][c4 * 4 + 1] = f2tff(v.y);
            ks[r][c4 * 4 + 2] = f2tff(v.z);
            ks[r][c4 * 4 + 3] = f2tff(v.w);
        }
        __syncthreads();

        // ctx += P @ V   (P: 16 x 128 per warp, V: 128 x 64)
#pragma unroll
        for (int k8 = 0; k8 < 16; k8++) {
            const int c0 = k8 * 8;
            uint32_t a[4];
            a[0] = __float_as_uint(ps[wrow + g][c0 + tg]);
            a[1] = __float_as_uint(ps[wrow + 8 + g][c0 + tg]);
            a[2] = __float_as_uint(ps[wrow + g][c0 + tg + 4]);
            a[3] = __float_as_uint(ps[wrow + 8 + g][c0 + tg + 4]);
#pragma unroll
            for (int nt2 = 0; nt2 < 8; nt2++) {
                uint32_t b[2] = {__float_as_uint(ks[c0 + tg][nt2 * 8 + g]),
                                 __float_as_uint(ks[c0 + tg + 4][nt2 * 8 + g])};
                mma8(ctx[nt2], a, b);
            }
        }
        __syncthreads();
    }

    // write ctx into merged [B,S,D] layout for the output projection
    const int b_ = bh >> 4, h_ = bh & 15;
    const int r0 = qt * 64 + wrow + g;
    const size_t crow = ((size_t)b_ * SQ + r0) * DM + h_ * 64;
#pragma unroll
    for (int nt2 = 0; nt2 < 8; nt2++) {
        int cc = nt2 * 8 + tg * 2;
        *(float2*)(g_ctx + crow + cc) = make_float2(ctx[nt2][0], ctx[nt2][1]);
        *(float2*)(g_ctx + crow + (size_t)8 * DM + cc) = make_float2(ctx[nt2][2], ctx[nt2][3]);
    }
}

extern "C" void kernel_launch(void* const* d_in, const int* in_sizes, int n_in,
                              void* d_out, int out_size)
{
    const float* Q   = (const float*)d_in[0];
    const float* K   = (const float*)d_in[1];
    const float* V   = (const float*)d_in[2];
    const float* Wq  = (const float*)d_in[3];
    const float* bq  = (const float*)d_in[4];
    const float* Wk  = (const float*)d_in[5];
    const float* bk  = (const float*)d_in[6];
    const float* Wv  = (const float*)d_in[7];
    const float* bv  = (const float*)d_in[8];
    const float* Wfc = (const float*)d_in[9];
    const float* bfc = (const float*)d_in[10];

    float* out  = (float*)d_out;
    float* attn = out + OUT_ELEMS;

    cudaFuncSetAttribute(attn_kernel, cudaFuncAttributeMaxDynamicSharedMemorySize, 86016);

    // QKV projections (z selects q/k/v), head-split outputs into g_q/g_k/g_v
    gemm_kernel<1><<<dim3(8, 32, 3), 256>>>(Q, K, V, Wq, Wk, Wv, bq, bk, bv, nullptr);
    // Fused two-pass attention: writes attn (normalized) + g_ctx
    attn_kernel<<<dim3(32, 32), 128, 86016>>>(attn);
    // Output projection
    gemm_kernel<0><<<dim3(8, 32, 1), 256>>>(nullptr, nullptr, nullptr,
                                            Wfc, nullptr, nullptr,
                                            bfc, nullptr, nullptr, out);
}